// round 1
// baseline (speedup 1.0000x reference)
#include <cuda_runtime.h>
#include <cuda_bf16.h>
#include <cstdint>

#define N_NODES 100000
#define N_EDGES 1600000
#define IN_C 128
#define OUT_C 128

// ---- scratch in __device__ globals (no cudaMalloc allowed) ----
__device__ float g_xw[(size_t)N_NODES * OUT_C];   // 51.2 MB
__device__ float g_dinv[N_NODES];
__device__ int   g_deg[N_NODES];

// ------------------------------------------------------------------
// 1) zero degree counters
__global__ void k_zero_deg() {
    int i = blockIdx.x * blockDim.x + threadIdx.x;
    if (i < N_NODES) g_deg[i] = 0;
}

// 2) count degrees (both endpoints of every undirected edge)
__global__ void k_count_deg(const int* __restrict__ ei) {
    int e = blockIdx.x * blockDim.x + threadIdx.x;
    if (e < N_EDGES) {
        atomicAdd(&g_deg[ei[e]], 1);
        atomicAdd(&g_deg[ei[N_EDGES + e]], 1);
    }
}

// 3) dinv[i] = rsqrt(deg[i] + 1)   (self-loop weight 1, deg+1 >= 1 always)
__global__ void k_dinv() {
    int i = blockIdx.x * blockDim.x + threadIdx.x;
    if (i < N_NODES) g_dinv[i] = rsqrtf((float)g_deg[i] + 1.0f);
}

// ------------------------------------------------------------------
// 4) GEMM: xw = x @ W   (x: [N,128], W: [128,128])
//    Block = 128 threads (one per output col), 32 rows per block.
//    x tile staged in shared; W reads are coalesced + L1-resident (64 KB).
#define GEMM_ROWS 32
__global__ void k_gemm(const float* __restrict__ x, const float* __restrict__ W) {
    __shared__ float xs[GEMM_ROWS][IN_C];
    const int row0 = blockIdx.x * GEMM_ROWS;
    const int tid  = threadIdx.x;  // 0..127

    #pragma unroll
    for (int i = tid; i < GEMM_ROWS * IN_C; i += 128) {
        int r = i >> 7, k = i & 127;
        xs[r][k] = x[(size_t)(row0 + r) * IN_C + k];
    }
    __syncthreads();

    float acc[GEMM_ROWS];
    #pragma unroll
    for (int r = 0; r < GEMM_ROWS; r++) acc[r] = 0.0f;

    const int j = tid;
    for (int k = 0; k < IN_C; k++) {
        float w = W[k * OUT_C + j];
        #pragma unroll
        for (int r = 0; r < GEMM_ROWS; r++) acc[r] += xs[r][k] * w;
    }

    #pragma unroll
    for (int r = 0; r < GEMM_ROWS; r++)
        g_xw[(size_t)(row0 + r) * OUT_C + j] = acc[r];
}

// ------------------------------------------------------------------
// 5) init output: y = dinv^2 * xw + b   (self-loop + bias; also un-poisons d_out)
__global__ void k_init_y(const float* __restrict__ b, float* __restrict__ y) {
    int i = blockIdx.x * blockDim.x + threadIdx.x;   // over N*128 = 12.8M
    if (i < N_NODES * OUT_C) {
        int node = i >> 7;
        int c    = i & 127;
        float d  = g_dinv[node];
        y[i] = d * d * g_xw[i] + b[c];
    }
}

// ------------------------------------------------------------------
// 6) scatter SpMM: for every directed edge (r,c): y[r] += dinv[r]*dinv[c]*xw[c]
//    One warp per directed edge; lane handles 4 contiguous floats (float4 gather).
__global__ void k_scatter(const int* __restrict__ ei, float* __restrict__ y) {
    const int gwarp = (blockIdx.x * blockDim.x + threadIdx.x) >> 5;
    const int lane  = threadIdx.x & 31;
    if (gwarp >= 2 * N_EDGES) return;

    int e, r, c;
    if (gwarp < N_EDGES) {
        e = gwarp;
        r = ei[e];
        c = ei[N_EDGES + e];
    } else {
        e = gwarp - N_EDGES;
        r = ei[N_EDGES + e];
        c = ei[e];
    }

    const float norm = g_dinv[r] * g_dinv[c];
    const float4 m = ((const float4*)(g_xw + (size_t)c * OUT_C))[lane];
    float* yp = y + (size_t)r * OUT_C + lane * 4;
    atomicAdd(yp + 0, norm * m.x);
    atomicAdd(yp + 1, norm * m.y);
    atomicAdd(yp + 2, norm * m.z);
    atomicAdd(yp + 3, norm * m.w);
}

// ------------------------------------------------------------------
extern "C" void kernel_launch(void* const* d_in, const int* in_sizes, int n_in,
                              void* d_out, int out_size) {
    const float* x  = (const float*)d_in[0];
    const float* W  = (const float*)d_in[1];
    const float* b  = (const float*)d_in[2];
    const int*   ei = (const int*)d_in[3];
    float* y = (float*)d_out;

    // degrees
    k_zero_deg<<<(N_NODES + 255) / 256, 256>>>();
    k_count_deg<<<(N_EDGES + 255) / 256, 256>>>(ei);
    k_dinv<<<(N_NODES + 255) / 256, 256>>>();

    // dense projection
    k_gemm<<<N_NODES / GEMM_ROWS, 128>>>(x, W);   // 100000 / 32 = 3125 exact

    // self-loop + bias init
    k_init_y<<<(N_NODES * OUT_C + 255) / 256, 256>>>(b, y);

    // edge scatter: 2E warps, 8 warps (256 threads) per block
    const long long total_warps = 2LL * N_EDGES;
    const int blocks = (int)((total_warps * 32 + 255) / 256);
    k_scatter<<<blocks, 256>>>(ei, y);
}

// round 2
// speedup vs baseline: 2.3009x; 2.3009x over previous
#include <cuda_runtime.h>
#include <cuda_bf16.h>
#include <cstdint>

#define N_NODES 100000
#define N_EDGES 1600000
#define IN_C 128
#define OUT_C 128
#define SCAN_T 1024

// ---- scratch in __device__ globals (no cudaMalloc allowed) ----
__device__ float g_xw[(size_t)N_NODES * OUT_C];   // 51.2 MB
__device__ float g_dinv[N_NODES];
__device__ int   g_deg[N_NODES];
__device__ int   g_off[N_NODES + 1];
__device__ int   g_cursor[N_NODES];
__device__ int   g_col[2 * N_EDGES];              // 12.8 MB

// ------------------------------------------------------------------
// 1) zero degree counters
__global__ void k_zero_deg() {
    int i = blockIdx.x * blockDim.x + threadIdx.x;
    if (i < N_NODES) g_deg[i] = 0;
}

// 2) count degrees (both endpoints of every undirected edge)
__global__ void k_count_deg(const int* __restrict__ ei) {
    int e = blockIdx.x * blockDim.x + threadIdx.x;
    if (e < N_EDGES) {
        atomicAdd(&g_deg[ei[e]], 1);
        atomicAdd(&g_deg[ei[N_EDGES + e]], 1);
    }
}

// ------------------------------------------------------------------
// 3) single-block exclusive scan of deg -> off; also dinv + cursor init.
//    100K elements, 1024 threads, each owns a contiguous chunk.
__global__ void k_scan_dinv() {
    __shared__ int s[SCAN_T];
    const int t = threadIdx.x;
    const int chunk = (N_NODES + SCAN_T - 1) / SCAN_T;   // 98
    const int lo = t * chunk;
    const int hi = (lo + chunk < N_NODES) ? (lo + chunk) : N_NODES;

    int sum = 0;
    for (int i = lo; i < hi; i++) sum += g_deg[i];
    s[t] = sum;
    __syncthreads();

    // Hillis-Steele inclusive scan over 1024 partials
    for (int d = 1; d < SCAN_T; d <<= 1) {
        int v = (t >= d) ? s[t - d] : 0;
        __syncthreads();
        s[t] += v;
        __syncthreads();
    }

    int base = (t == 0) ? 0 : s[t - 1];   // exclusive prefix of this chunk
    for (int i = lo; i < hi; i++) {
        int d = g_deg[i];
        g_off[i]    = base;
        g_cursor[i] = 0;
        g_dinv[i]   = rsqrtf((float)d + 1.0f);
        base += d;
    }
    if (t == SCAN_T - 1) g_off[N_NODES] = base;  // == 2*N_EDGES
}

// 4) fill CSR column lists (order within a row is nondeterministic; the
//    per-row float sum stays within rel-err tolerance)
__global__ void k_fill(const int* __restrict__ ei) {
    int e = blockIdx.x * blockDim.x + threadIdx.x;
    if (e < N_EDGES) {
        int a = ei[e];
        int b = ei[N_EDGES + e];
        int pa = atomicAdd(&g_cursor[a], 1);
        g_col[g_off[a] + pa] = b;
        int pb = atomicAdd(&g_cursor[b], 1);
        g_col[g_off[b] + pb] = a;
    }
}

// ------------------------------------------------------------------
// 5) GEMM: xw = x @ W. 128 threads (one out-col each), 32 rows/block.
//    float4 shared reads: 1 LDS.128 feeds 4 FFMAs -> FFMA-bound.
#define GEMM_ROWS 32
__global__ void k_gemm(const float* __restrict__ x, const float* __restrict__ W) {
    __shared__ float xs[GEMM_ROWS][IN_C];
    const int row0 = blockIdx.x * GEMM_ROWS;
    const int tid  = threadIdx.x;  // 0..127

    #pragma unroll
    for (int i = tid; i < GEMM_ROWS * IN_C; i += 128) {
        int r = i >> 7, k = i & 127;
        xs[r][k] = x[(size_t)(row0 + r) * IN_C + k];
    }
    __syncthreads();

    float acc[GEMM_ROWS];
    #pragma unroll
    for (int r = 0; r < GEMM_ROWS; r++) acc[r] = 0.0f;

    const int j = tid;
    for (int k = 0; k < IN_C; k += 4) {
        const float w0 = W[(k + 0) * OUT_C + j];
        const float w1 = W[(k + 1) * OUT_C + j];
        const float w2 = W[(k + 2) * OUT_C + j];
        const float w3 = W[(k + 3) * OUT_C + j];
        #pragma unroll
        for (int r = 0; r < GEMM_ROWS; r++) {
            float4 xv = *(const float4*)&xs[r][k];
            acc[r] = fmaf(xv.x, w0,
                     fmaf(xv.y, w1,
                     fmaf(xv.z, w2,
                     fmaf(xv.w, w3, acc[r]))));
        }
    }

    #pragma unroll
    for (int r = 0; r < GEMM_ROWS; r++)
        g_xw[(size_t)(row0 + r) * OUT_C + j] = acc[r];
}

// ------------------------------------------------------------------
// 6) gather SpMM + self-loop + bias, fused. One warp per destination node;
//    lane owns 4 contiguous floats of the 128-wide row (float4).
//    y[n] = dinv[n] * (sum_c dinv[c]*xw[c]) + dinv[n]^2*xw[n] + b
__global__ void k_gather(const float* __restrict__ b, float* __restrict__ y) {
    const int node = (blockIdx.x * blockDim.x + threadIdx.x) >> 5;
    const int lane = threadIdx.x & 31;
    if (node >= N_NODES) return;

    const int beg = g_off[node];
    const int end = g_off[node + 1];

    float4 acc = make_float4(0.f, 0.f, 0.f, 0.f);

    // software-pipeline the column index to overlap the dependent load chain
    int c = (beg < end) ? g_col[beg] : 0;
    for (int j = beg; j < end; j++) {
        const int cn = (j + 1 < end) ? g_col[j + 1] : 0;
        const float w = g_dinv[c];
        const float4 v = ((const float4*)(g_xw + (size_t)c * OUT_C))[lane];
        acc.x += w * v.x;
        acc.y += w * v.y;
        acc.z += w * v.z;
        acc.w += w * v.w;
        c = cn;
    }

    const float dn = g_dinv[node];
    const float4 sv = ((const float4*)(g_xw + (size_t)node * OUT_C))[lane];
    const float4 bv = ((const float4*)b)[lane];
    float4 o;
    o.x = dn * acc.x + dn * dn * sv.x + bv.x;
    o.y = dn * acc.y + dn * dn * sv.y + bv.y;
    o.z = dn * acc.z + dn * dn * sv.z + bv.z;
    o.w = dn * acc.w + dn * dn * sv.w + bv.w;
    ((float4*)(y + (size_t)node * OUT_C))[lane] = o;
}

// ------------------------------------------------------------------
extern "C" void kernel_launch(void* const* d_in, const int* in_sizes, int n_in,
                              void* d_out, int out_size) {
    const float* x  = (const float*)d_in[0];
    const float* W  = (const float*)d_in[1];
    const float* b  = (const float*)d_in[2];
    const int*   ei = (const int*)d_in[3];
    float* y = (float*)d_out;

    // CSR build
    k_zero_deg<<<(N_NODES + 255) / 256, 256>>>();
    k_count_deg<<<(N_EDGES + 255) / 256, 256>>>(ei);
    k_scan_dinv<<<1, SCAN_T>>>();
    k_fill<<<(N_EDGES + 255) / 256, 256>>>(ei);

    // dense projection (independent of CSR; stream order is fine)
    k_gemm<<<N_NODES / GEMM_ROWS, 128>>>(x, W);   // 100000/32 = 3125 exact

    // fused gather + self-loop + bias: one warp per node, 8 warps/block
    const int gather_blocks = (N_NODES * 32 + 255) / 256;
    k_gather<<<gather_blocks, 256>>>(b, y);
}

// round 3
// speedup vs baseline: 2.5287x; 1.0990x over previous
#include <cuda_runtime.h>
#include <cuda_fp16.h>
#include <cstdint>

#define N_NODES 100000
#define N_EDGES 1600000
#define IN_C 128
#define OUT_C 128
#define SCAN_T 1024

// ---- scratch in __device__ globals (no cudaMalloc allowed) ----
__device__ __half g_xwh[(size_t)N_NODES * OUT_C]; // 25.6 MB, prescaled by dinv
__device__ float  g_dinv[N_NODES];
__device__ int    g_deg[N_NODES];
__device__ int    g_off[N_NODES + 1];
__device__ int    g_cursor[N_NODES];
__device__ int    g_col[2 * N_EDGES];             // 12.8 MB

// ------------------------------------------------------------------
// 1) zero degree counters
__global__ void k_zero_deg() {
    int i = blockIdx.x * blockDim.x + threadIdx.x;
    if (i < N_NODES) g_deg[i] = 0;
}

// 2) count degrees (both endpoints of every undirected edge)
__global__ void k_count_deg(const int* __restrict__ ei) {
    int e = blockIdx.x * blockDim.x + threadIdx.x;
    if (e < N_EDGES) {
        atomicAdd(&g_deg[ei[e]], 1);
        atomicAdd(&g_deg[ei[N_EDGES + e]], 1);
    }
}

// ------------------------------------------------------------------
// 3) single-block exclusive scan of deg -> off; also dinv + cursor init.
__global__ void k_scan_dinv() {
    __shared__ int s[SCAN_T];
    const int t = threadIdx.x;
    const int chunk = (N_NODES + SCAN_T - 1) / SCAN_T;   // 98
    const int lo = t * chunk;
    const int hi = (lo + chunk < N_NODES) ? (lo + chunk) : N_NODES;

    int sum = 0;
    for (int i = lo; i < hi; i++) sum += g_deg[i];
    s[t] = sum;
    __syncthreads();

    for (int d = 1; d < SCAN_T; d <<= 1) {
        int v = (t >= d) ? s[t - d] : 0;
        __syncthreads();
        s[t] += v;
        __syncthreads();
    }

    int base = (t == 0) ? 0 : s[t - 1];
    for (int i = lo; i < hi; i++) {
        int d = g_deg[i];
        g_off[i]    = base;
        g_cursor[i] = 0;
        g_dinv[i]   = rsqrtf((float)d + 1.0f);
        base += d;
    }
    if (t == SCAN_T - 1) g_off[N_NODES] = base;  // == 2*N_EDGES
}

// 4) fill CSR column lists
__global__ void k_fill(const int* __restrict__ ei) {
    int e = blockIdx.x * blockDim.x + threadIdx.x;
    if (e < N_EDGES) {
        int a = ei[e];
        int b = ei[N_EDGES + e];
        int pa = atomicAdd(&g_cursor[a], 1);
        g_col[g_off[a] + pa] = b;
        int pb = atomicAdd(&g_cursor[b], 1);
        g_col[g_off[b] + pb] = a;
    }
}

// ------------------------------------------------------------------
// 5) GEMM: xwh = half(dinv[row] * (x @ W)). 128 threads (one out-col each),
//    32 rows/block; float4 shared reads keep it FFMA-bound.
#define GEMM_ROWS 32
__global__ void k_gemm(const float* __restrict__ x, const float* __restrict__ W) {
    __shared__ float xs[GEMM_ROWS][IN_C];
    __shared__ float dv[GEMM_ROWS];
    const int row0 = blockIdx.x * GEMM_ROWS;
    const int tid  = threadIdx.x;  // 0..127

    if (tid < GEMM_ROWS) dv[tid] = g_dinv[row0 + tid];

    #pragma unroll
    for (int i = tid; i < GEMM_ROWS * IN_C; i += 128) {
        int r = i >> 7, k = i & 127;
        xs[r][k] = x[(size_t)(row0 + r) * IN_C + k];
    }
    __syncthreads();

    float acc[GEMM_ROWS];
    #pragma unroll
    for (int r = 0; r < GEMM_ROWS; r++) acc[r] = 0.0f;

    const int j = tid;
    for (int k = 0; k < IN_C; k += 4) {
        const float w0 = W[(k + 0) * OUT_C + j];
        const float w1 = W[(k + 1) * OUT_C + j];
        const float w2 = W[(k + 2) * OUT_C + j];
        const float w3 = W[(k + 3) * OUT_C + j];
        #pragma unroll
        for (int r = 0; r < GEMM_ROWS; r++) {
            float4 xv = *(const float4*)&xs[r][k];
            acc[r] = fmaf(xv.x, w0,
                     fmaf(xv.y, w1,
                     fmaf(xv.z, w2,
                     fmaf(xv.w, w3, acc[r]))));
        }
    }

    #pragma unroll
    for (int r = 0; r < GEMM_ROWS; r++)
        g_xwh[(size_t)(row0 + r) * OUT_C + j] = __float2half(acc[r] * dv[r]);
}

// ------------------------------------------------------------------
// 6) gather SpMM + self-loop + bias, fused. One warp per destination node;
//    lane owns 4 contiguous output floats (one 8B half4 load per neighbor).
//    y[n] = dinv[n] * (sum_c xwh[c] + xwh[n]) + b
__global__ void k_gather(const float* __restrict__ b, float* __restrict__ y) {
    const int node = (blockIdx.x * blockDim.x + threadIdx.x) >> 5;
    const int lane = threadIdx.x & 31;
    if (node >= N_NODES) return;

    const int beg = g_off[node];
    const int end = g_off[node + 1];

    float ax = 0.f, ay = 0.f, az = 0.f, aw = 0.f;

    #pragma unroll 4
    for (int j = beg; j < end; j++) {
        const int c = g_col[j];
        const uint2 u = ((const uint2*)(g_xwh + (size_t)c * OUT_C))[lane];
        const float2 f0 = __half22float2(*(const __half2*)&u.x);
        const float2 f1 = __half22float2(*(const __half2*)&u.y);
        ax += f0.x; ay += f0.y; az += f1.x; aw += f1.y;
    }

    // self-loop: + xwh[node] (already prescaled by dinv[node])
    {
        const uint2 u = ((const uint2*)(g_xwh + (size_t)node * OUT_C))[lane];
        const float2 f0 = __half22float2(*(const __half2*)&u.x);
        const float2 f1 = __half22float2(*(const __half2*)&u.y);
        ax += f0.x; ay += f0.y; az += f1.x; aw += f1.y;
    }

    const float dn = g_dinv[node];
    const float4 bv = ((const float4*)b)[lane];
    float4 o;
    o.x = dn * ax + bv.x;
    o.y = dn * ay + bv.y;
    o.z = dn * az + bv.z;
    o.w = dn * aw + bv.w;
    ((float4*)(y + (size_t)node * OUT_C))[lane] = o;
}

// ------------------------------------------------------------------
extern "C" void kernel_launch(void* const* d_in, const int* in_sizes, int n_in,
                              void* d_out, int out_size) {
    const float* x  = (const float*)d_in[0];
    const float* W  = (const float*)d_in[1];
    const float* b  = (const float*)d_in[2];
    const int*   ei = (const int*)d_in[3];
    float* y = (float*)d_out;

    // CSR build + dinv
    k_zero_deg<<<(N_NODES + 255) / 256, 256>>>();
    k_count_deg<<<(N_EDGES + 255) / 256, 256>>>(ei);
    k_scan_dinv<<<1, SCAN_T>>>();

    // dense projection, prescaled by dinv, stored fp16 (needs dinv ready)
    k_gemm<<<N_NODES / GEMM_ROWS, 128>>>(x, W);   // 100000/32 = 3125 exact

    // CSR fill (independent of GEMM, same stream)
    k_fill<<<(N_EDGES + 255) / 256, 256>>>(ei);

    // fused gather + self-loop + bias: one warp per node
    const int gather_blocks = (N_NODES * 32 + 255) / 256;
    k_gather<<<gather_blocks, 256>>>(b, y);
}

// round 4
// speedup vs baseline: 4.6904x; 1.8549x over previous
#include <cuda_runtime.h>
#include <cuda_fp16.h>
#include <cstdint>

#define N_NODES 100000
#define N_EDGES 1600000
#define IN_C 128
#define OUT_C 128

#define SCAN_CHUNK 1024
#define SCAN_BLOCKS ((N_NODES + SCAN_CHUNK - 1) / SCAN_CHUNK)   // 98

// ---- scratch in __device__ globals (no cudaMalloc allowed) ----
__device__ __half g_xwh[(size_t)N_NODES * OUT_C]; // 25.6 MB, prescaled by dinv
__device__ float  g_dinv[N_NODES];
__device__ int    g_deg[N_NODES];
__device__ int    g_off[N_NODES + 1];
__device__ int    g_cursor[N_NODES];
__device__ int    g_col[2 * N_EDGES];             // 12.8 MB
__device__ int    g_bsum[SCAN_BLOCKS];
__device__ int    g_boff[SCAN_BLOCKS];

// ------------------------------------------------------------------
// 1) zero degree counters
__global__ void k_zero_deg() {
    int i = blockIdx.x * blockDim.x + threadIdx.x;
    if (i < N_NODES) g_deg[i] = 0;
}

// 2) count degrees (both endpoints of every undirected edge)
__global__ void k_count_deg(const int* __restrict__ ei) {
    int e = blockIdx.x * blockDim.x + threadIdx.x;
    if (e < N_EDGES) {
        atomicAdd(&g_deg[ei[e]], 1);
        atomicAdd(&g_deg[ei[N_EDGES + e]], 1);
    }
}

// ------------------------------------------------------------------
// 3a) per-block sums of deg over contiguous 1024-element tiles (coalesced)
__global__ void k_block_sum() {
    __shared__ int s[SCAN_CHUNK];
    const int t = threadIdx.x;
    const int i = blockIdx.x * SCAN_CHUNK + t;
    s[t] = (i < N_NODES) ? g_deg[i] : 0;
    __syncthreads();
    for (int d = SCAN_CHUNK / 2; d > 0; d >>= 1) {
        if (t < d) s[t] += s[t + d];
        __syncthreads();
    }
    if (t == 0) g_bsum[blockIdx.x] = s[0];
}

// 3b) single-warp-ish exclusive scan of the 98 block sums
__global__ void k_scan_small() {
    __shared__ int s[128];
    const int t = threadIdx.x;
    s[t] = (t < SCAN_BLOCKS) ? g_bsum[t] : 0;
    __syncthreads();
    for (int d = 1; d < 128; d <<= 1) {
        int v = (t >= d) ? s[t - d] : 0;
        __syncthreads();
        s[t] += v;
        __syncthreads();
    }
    if (t < SCAN_BLOCKS) g_boff[t] = (t == 0) ? 0 : s[t - 1];
    if (t == 127) g_off[N_NODES] = s[SCAN_BLOCKS - 1];  // total == 2*N_EDGES
}

// 3c) per-block apply: block-local exclusive scan + write off/cursor/dinv
__global__ void k_scan_apply() {
    __shared__ int s[SCAN_CHUNK];
    const int t = threadIdx.x;
    const int i = blockIdx.x * SCAN_CHUNK + t;
    const int d = (i < N_NODES) ? g_deg[i] : 0;
    s[t] = d;
    __syncthreads();
    // Hillis-Steele inclusive scan
    for (int k = 1; k < SCAN_CHUNK; k <<= 1) {
        int v = (t >= k) ? s[t - k] : 0;
        __syncthreads();
        s[t] += v;
        __syncthreads();
    }
    if (i < N_NODES) {
        const int excl = s[t] - d;
        g_off[i]    = g_boff[blockIdx.x] + excl;
        g_cursor[i] = 0;
        g_dinv[i]   = rsqrtf((float)d + 1.0f);
    }
}

// 4) fill CSR column lists
__global__ void k_fill(const int* __restrict__ ei) {
    int e = blockIdx.x * blockDim.x + threadIdx.x;
    if (e < N_EDGES) {
        int a = ei[e];
        int b = ei[N_EDGES + e];
        int pa = atomicAdd(&g_cursor[a], 1);
        g_col[g_off[a] + pa] = b;
        int pb = atomicAdd(&g_cursor[b], 1);
        g_col[g_off[b] + pb] = a;
    }
}

// ------------------------------------------------------------------
// 5) GEMM: xwh = half(dinv[row] * (x @ W)). Near scalar-fp32 FFMA peak.
#define GEMM_ROWS 32
__global__ void k_gemm(const float* __restrict__ x, const float* __restrict__ W) {
    __shared__ float xs[GEMM_ROWS][IN_C];
    __shared__ float dv[GEMM_ROWS];
    const int row0 = blockIdx.x * GEMM_ROWS;
    const int tid  = threadIdx.x;  // 0..127

    if (tid < GEMM_ROWS) dv[tid] = g_dinv[row0 + tid];

    #pragma unroll
    for (int i = tid; i < GEMM_ROWS * IN_C; i += 128) {
        int r = i >> 7, k = i & 127;
        xs[r][k] = x[(size_t)(row0 + r) * IN_C + k];
    }
    __syncthreads();

    float acc[GEMM_ROWS];
    #pragma unroll
    for (int r = 0; r < GEMM_ROWS; r++) acc[r] = 0.0f;

    const int j = tid;
    for (int k = 0; k < IN_C; k += 4) {
        const float w0 = W[(k + 0) * OUT_C + j];
        const float w1 = W[(k + 1) * OUT_C + j];
        const float w2 = W[(k + 2) * OUT_C + j];
        const float w3 = W[(k + 3) * OUT_C + j];
        #pragma unroll
        for (int r = 0; r < GEMM_ROWS; r++) {
            float4 xv = *(const float4*)&xs[r][k];
            acc[r] = fmaf(xv.x, w0,
                     fmaf(xv.y, w1,
                     fmaf(xv.z, w2,
                     fmaf(xv.w, w3, acc[r]))));
        }
    }

    #pragma unroll
    for (int r = 0; r < GEMM_ROWS; r++)
        g_xwh[(size_t)(row0 + r) * OUT_C + j] = __float2half(acc[r] * dv[r]);
}

// ------------------------------------------------------------------
// 6) gather SpMM + self-loop + bias. One warp per destination node; lane owns
//    4 output floats (8B half4 load per neighbor). Column indices batched 8
//    at a time into registers to raise MLP on the dependent row loads.
__global__ void k_gather(const float* __restrict__ b, float* __restrict__ y) {
    const int node = (blockIdx.x * blockDim.x + threadIdx.x) >> 5;
    const int lane = threadIdx.x & 31;
    if (node >= N_NODES) return;

    const int beg = g_off[node];
    const int end = g_off[node + 1];

    float ax = 0.f, ay = 0.f, az = 0.f, aw = 0.f;

    int j = beg;
    for (; j + 8 <= end; j += 8) {
        int c0 = g_col[j + 0], c1 = g_col[j + 1], c2 = g_col[j + 2], c3 = g_col[j + 3];
        int c4 = g_col[j + 4], c5 = g_col[j + 5], c6 = g_col[j + 6], c7 = g_col[j + 7];
        uint2 u0 = ((const uint2*)(g_xwh + (size_t)c0 * OUT_C))[lane];
        uint2 u1 = ((const uint2*)(g_xwh + (size_t)c1 * OUT_C))[lane];
        uint2 u2 = ((const uint2*)(g_xwh + (size_t)c2 * OUT_C))[lane];
        uint2 u3 = ((const uint2*)(g_xwh + (size_t)c3 * OUT_C))[lane];
        uint2 u4 = ((const uint2*)(g_xwh + (size_t)c4 * OUT_C))[lane];
        uint2 u5 = ((const uint2*)(g_xwh + (size_t)c5 * OUT_C))[lane];
        uint2 u6 = ((const uint2*)(g_xwh + (size_t)c6 * OUT_C))[lane];
        uint2 u7 = ((const uint2*)(g_xwh + (size_t)c7 * OUT_C))[lane];
        #define ACCUM(u) { \
            float2 f0 = __half22float2(*(const __half2*)&(u).x); \
            float2 f1 = __half22float2(*(const __half2*)&(u).y); \
            ax += f0.x; ay += f0.y; az += f1.x; aw += f1.y; }
        ACCUM(u0) ACCUM(u1) ACCUM(u2) ACCUM(u3)
        ACCUM(u4) ACCUM(u5) ACCUM(u6) ACCUM(u7)
    }
    for (; j < end; j++) {
        const int c = g_col[j];
        uint2 u = ((const uint2*)(g_xwh + (size_t)c * OUT_C))[lane];
        ACCUM(u)
    }
    // self-loop: + xwh[node] (already prescaled by dinv[node])
    {
        uint2 u = ((const uint2*)(g_xwh + (size_t)node * OUT_C))[lane];
        ACCUM(u)
    }
    #undef ACCUM

    const float dn = g_dinv[node];
    const float4 bv = ((const float4*)b)[lane];
    float4 o;
    o.x = dn * ax + bv.x;
    o.y = dn * ay + bv.y;
    o.z = dn * az + bv.z;
    o.w = dn * aw + bv.w;
    ((float4*)(y + (size_t)node * OUT_C))[lane] = o;
}

// ------------------------------------------------------------------
extern "C" void kernel_launch(void* const* d_in, const int* in_sizes, int n_in,
                              void* d_out, int out_size) {
    const float* x  = (const float*)d_in[0];
    const float* W  = (const float*)d_in[1];
    const float* b  = (const float*)d_in[2];
    const int*   ei = (const int*)d_in[3];
    float* y = (float*)d_out;

    // CSR build + dinv (coalesced 3-phase scan)
    k_zero_deg<<<(N_NODES + 255) / 256, 256>>>();
    k_count_deg<<<(N_EDGES + 255) / 256, 256>>>(ei);
    k_block_sum<<<SCAN_BLOCKS, SCAN_CHUNK>>>();
    k_scan_small<<<1, 128>>>();
    k_scan_apply<<<SCAN_BLOCKS, SCAN_CHUNK>>>();

    // dense projection, prescaled by dinv, stored fp16 (needs dinv ready)
    k_gemm<<<N_NODES / GEMM_ROWS, 128>>>(x, W);   // 100000/32 = 3125 exact

    // CSR fill
    k_fill<<<(N_EDGES + 255) / 256, 256>>>(ei);

    // fused gather + self-loop + bias: one warp per node
    const int gather_blocks = (N_NODES * 32 + 255) / 256;
    k_gather<<<gather_blocks, 256>>>(b, y);
}

// round 6
// speedup vs baseline: 6.0951x; 1.2995x over previous
#include <cuda_runtime.h>
#include <cuda_fp16.h>
#include <cstdint>

#define N_NODES 100000
#define N_EDGES 1600000
#define IN_C 128
#define OUT_C 128

#define SCAN_CHUNK 1024
#define SCAN_BLOCKS ((N_NODES + SCAN_CHUNK - 1) / SCAN_CHUNK)   // 98

// ---- scratch in __device__ globals (no cudaMalloc allowed) ----
__device__ __half g_xwh[(size_t)N_NODES * OUT_C]; // 25.6 MB, prescaled by dinv
__device__ float  g_dinv[N_NODES];
__device__ int    g_deg[N_NODES];
__device__ int    g_off[N_NODES + 1];
__device__ int    g_cursor[N_NODES];
__device__ int    g_col[2 * N_EDGES];             // 12.8 MB
__device__ int    g_bsum[SCAN_BLOCKS];
__device__ int    g_boff[SCAN_BLOCKS];

__device__ __forceinline__ unsigned h2_to_u32(__half2 h) {
    return *reinterpret_cast<unsigned*>(&h);
}

// ------------------------------------------------------------------
__global__ void k_zero_deg() {
    int i = blockIdx.x * blockDim.x + threadIdx.x;
    if (i < N_NODES) g_deg[i] = 0;
}

__global__ void k_count_deg(const int* __restrict__ ei) {
    int e = blockIdx.x * blockDim.x + threadIdx.x;
    if (e < N_EDGES) {
        atomicAdd(&g_deg[ei[e]], 1);
        atomicAdd(&g_deg[ei[N_EDGES + e]], 1);
    }
}

// 3a) per-block sums of deg (coalesced)
__global__ void k_block_sum() {
    __shared__ int s[SCAN_CHUNK];
    const int t = threadIdx.x;
    const int i = blockIdx.x * SCAN_CHUNK + t;
    s[t] = (i < N_NODES) ? g_deg[i] : 0;
    __syncthreads();
    for (int d = SCAN_CHUNK / 2; d > 0; d >>= 1) {
        if (t < d) s[t] += s[t + d];
        __syncthreads();
    }
    if (t == 0) g_bsum[blockIdx.x] = s[0];
}

// 3b) tiny exclusive scan of the 98 block sums
__global__ void k_scan_small() {
    __shared__ int s[128];
    const int t = threadIdx.x;
    s[t] = (t < SCAN_BLOCKS) ? g_bsum[t] : 0;
    __syncthreads();
    for (int d = 1; d < 128; d <<= 1) {
        int v = (t >= d) ? s[t - d] : 0;
        __syncthreads();
        s[t] += v;
        __syncthreads();
    }
    if (t < SCAN_BLOCKS) g_boff[t] = (t == 0) ? 0 : s[t - 1];
    if (t == 127) g_off[N_NODES] = s[SCAN_BLOCKS - 1];
}

// 3c) per-block apply: local scan + write off/cursor/dinv
__global__ void k_scan_apply() {
    __shared__ int s[SCAN_CHUNK];
    const int t = threadIdx.x;
    const int i = blockIdx.x * SCAN_CHUNK + t;
    const int d = (i < N_NODES) ? g_deg[i] : 0;
    s[t] = d;
    __syncthreads();
    for (int k = 1; k < SCAN_CHUNK; k <<= 1) {
        int v = (t >= k) ? s[t - k] : 0;
        __syncthreads();
        s[t] += v;
        __syncthreads();
    }
    if (i < N_NODES) {
        const int excl = s[t] - d;
        g_off[i]    = g_boff[blockIdx.x] + excl;
        g_cursor[i] = 0;
        g_dinv[i]   = rsqrtf((float)d + 1.0f);
    }
}

// 4) fill CSR column lists
__global__ void k_fill(const int* __restrict__ ei) {
    int e = blockIdx.x * blockDim.x + threadIdx.x;
    if (e < N_EDGES) {
        int a = ei[e];
        int b = ei[N_EDGES + e];
        int pa = atomicAdd(&g_cursor[a], 1);
        g_col[g_off[a] + pa] = b;
        int pb = atomicAdd(&g_cursor[b], 1);
        g_col[g_off[b] + pb] = a;
    }
}

// ------------------------------------------------------------------
// 5) Tensor-core GEMM: xwh = half(dinv[row] * (x @ W)), fp32 accumulate.
//    Block = 128 threads = 4 warps; block tile M=64; warp tile m16 x n128.
//    W^T staged in shared as half with +8-half pad (conflict-free frags);
//    A fragments built straight from global float2 loads of x.
#define GEMM_M_BLK 64
#define WT_PAD 8
#define WT_LD (IN_C + WT_PAD)   // 136 halves row stride

__global__ __launch_bounds__(128, 1) void k_gemm(const float* __restrict__ x,
                                                 const float* __restrict__ W) {
    __shared__ __half wt[OUT_C][WT_LD];   // W^T: wt[n][k]

    const int tid  = threadIdx.x;
    const int wid  = tid >> 5;
    const int lane = tid & 31;

    // stage W^T into shared (fp32 -> fp16), coalesced global reads
    for (int i = tid; i < IN_C * OUT_C; i += 128) {
        int k = i >> 7;          // 0..127
        int n = i & 127;
        wt[n][k] = __float2half(W[(size_t)k * OUT_C + n]);
    }
    __syncthreads();

    const int row_base = blockIdx.x * GEMM_M_BLK + wid * 16;
    const int qr = lane >> 2;          // 0..7
    const int qc = lane & 3;           // 0..3
    const int r0 = row_base + qr;      // rows for a0/a2, c0/c1
    const int r1 = r0 + 8;             // rows for a1/a3, c2/c3
    const int r0c = (r0 < N_NODES) ? r0 : (N_NODES - 1);
    const int r1c = (r1 < N_NODES) ? r1 : (N_NODES - 1);
    const float* xr0 = x + (size_t)r0c * IN_C;
    const float* xr1 = x + (size_t)r1c * IN_C;

    float acc[16][4];
    #pragma unroll
    for (int nt = 0; nt < 16; nt++)
        #pragma unroll
        for (int q = 0; q < 4; q++) acc[nt][q] = 0.0f;

    #pragma unroll
    for (int ks = 0; ks < IN_C / 16; ks++) {
        const int k0 = ks * 16 + qc * 2;
        // A fragment: 4 x half2 built from global float2 loads
        float2 f;
        f = *(const float2*)(xr0 + k0);     unsigned a0 = h2_to_u32(__float22half2_rn(f));
        f = *(const float2*)(xr1 + k0);     unsigned a1 = h2_to_u32(__float22half2_rn(f));
        f = *(const float2*)(xr0 + k0 + 8); unsigned a2 = h2_to_u32(__float22half2_rn(f));
        f = *(const float2*)(xr1 + k0 + 8); unsigned a3 = h2_to_u32(__float22half2_rn(f));

        #pragma unroll
        for (int nt = 0; nt < 16; nt++) {
            const int n = nt * 8 + qr;
            unsigned b0 = *(const unsigned*)&wt[n][k0];
            unsigned b1 = *(const unsigned*)&wt[n][k0 + 8];
            asm volatile(
                "mma.sync.aligned.m16n8k16.row.col.f32.f16.f16.f32 "
                "{%0,%1,%2,%3}, {%4,%5,%6,%7}, {%8,%9}, {%0,%1,%2,%3};\n"
                : "+f"(acc[nt][0]), "+f"(acc[nt][1]), "+f"(acc[nt][2]), "+f"(acc[nt][3])
                : "r"(a0), "r"(a1), "r"(a2), "r"(a3), "r"(b0), "r"(b1));
        }
    }

    // epilogue: scale by dinv[row], convert to half, store half2
    const float d0 = g_dinv[r0c];
    const float d1 = g_dinv[r1c];
    #pragma unroll
    for (int nt = 0; nt < 16; nt++) {
        const int n = nt * 8 + qc * 2;
        if (r0 < N_NODES) {
            __half2 h = __floats2half2_rn(acc[nt][0] * d0, acc[nt][1] * d0);
            *(__half2*)(g_xwh + (size_t)r0 * OUT_C + n) = h;
        }
        if (r1 < N_NODES) {
            __half2 h = __floats2half2_rn(acc[nt][2] * d1, acc[nt][3] * d1);
            *(__half2*)(g_xwh + (size_t)r1 * OUT_C + n) = h;
        }
    }
}

// ------------------------------------------------------------------
// 6) gather SpMM + self-loop + bias. One warp per destination node.
__global__ void k_gather(const float* __restrict__ b, float* __restrict__ y) {
    const int node = (blockIdx.x * blockDim.x + threadIdx.x) >> 5;
    const int lane = threadIdx.x & 31;
    if (node >= N_NODES) return;

    const int beg = g_off[node];
    const int end = g_off[node + 1];

    float ax = 0.f, ay = 0.f, az = 0.f, aw = 0.f;

    int j = beg;
    for (; j + 8 <= end; j += 8) {
        int c0 = g_col[j + 0], c1 = g_col[j + 1], c2 = g_col[j + 2], c3 = g_col[j + 3];
        int c4 = g_col[j + 4], c5 = g_col[j + 5], c6 = g_col[j + 6], c7 = g_col[j + 7];
        uint2 u0 = ((const uint2*)(g_xwh + (size_t)c0 * OUT_C))[lane];
        uint2 u1 = ((const uint2*)(g_xwh + (size_t)c1 * OUT_C))[lane];
        uint2 u2 = ((const uint2*)(g_xwh + (size_t)c2 * OUT_C))[lane];
        uint2 u3 = ((const uint2*)(g_xwh + (size_t)c3 * OUT_C))[lane];
        uint2 u4 = ((const uint2*)(g_xwh + (size_t)c4 * OUT_C))[lane];
        uint2 u5 = ((const uint2*)(g_xwh + (size_t)c5 * OUT_C))[lane];
        uint2 u6 = ((const uint2*)(g_xwh + (size_t)c6 * OUT_C))[lane];
        uint2 u7 = ((const uint2*)(g_xwh + (size_t)c7 * OUT_C))[lane];
        #define ACCUM(u) { \
            float2 f0 = __half22float2(*(const __half2*)&(u).x); \
            float2 f1 = __half22float2(*(const __half2*)&(u).y); \
            ax += f0.x; ay += f0.y; az += f1.x; aw += f1.y; }
        ACCUM(u0) ACCUM(u1) ACCUM(u2) ACCUM(u3)
        ACCUM(u4) ACCUM(u5) ACCUM(u6) ACCUM(u7)
    }
    for (; j < end; j++) {
        const int c = g_col[j];
        uint2 u = ((const uint2*)(g_xwh + (size_t)c * OUT_C))[lane];
        ACCUM(u)
    }
    {
        uint2 u = ((const uint2*)(g_xwh + (size_t)node * OUT_C))[lane];
        ACCUM(u)
    }
    #undef ACCUM

    const float dn = g_dinv[node];
    const float4 bv = ((const float4*)b)[lane];
    float4 o;
    o.x = dn * ax + bv.x;
    o.y = dn * ay + bv.y;
    o.z = dn * az + bv.z;
    o.w = dn * aw + bv.w;
    ((float4*)(y + (size_t)node * OUT_C))[lane] = o;
}

// ------------------------------------------------------------------
extern "C" void kernel_launch(void* const* d_in, const int* in_sizes, int n_in,
                              void* d_out, int out_size) {
    const float* x  = (const float*)d_in[0];
    const float* W  = (const float*)d_in[1];
    const float* b  = (const float*)d_in[2];
    const int*   ei = (const int*)d_in[3];
    float* y = (float*)d_out;

    // CSR build + dinv
    k_zero_deg<<<(N_NODES + 255) / 256, 256>>>();
    k_count_deg<<<(N_EDGES + 255) / 256, 256>>>(ei);
    k_block_sum<<<SCAN_BLOCKS, SCAN_CHUNK>>>();
    k_scan_small<<<1, 128>>>();
    k_scan_apply<<<SCAN_BLOCKS, SCAN_CHUNK>>>();

    // tensor-core dense projection (needs dinv ready)
    const int gemm_blocks = (N_NODES + GEMM_M_BLK - 1) / GEMM_M_BLK;  // 1563
    k_gemm<<<gemm_blocks, 128>>>(x, W);

    // CSR fill
    k_fill<<<(N_EDGES + 255) / 256, 256>>>(ei);

    // fused gather + self-loop + bias: one warp per node
    const int gather_blocks = (N_NODES * 32 + 255) / 256;
    k_gather<<<gather_blocks, 256>>>(b, y);
}

// round 7
// speedup vs baseline: 6.1467x; 1.0085x over previous
#include <cuda_runtime.h>
#include <cuda_fp16.h>
#include <cstdint>

#define N_NODES 100000
#define N_EDGES 1600000
#define IN_C 128
#define OUT_C 128

#define SCAN_CHUNK 1024
#define SCAN_BLOCKS ((N_NODES + SCAN_CHUNK - 1) / SCAN_CHUNK)   // 98

// ---- scratch in __device__ globals (no cudaMalloc allowed) ----
__device__ __half g_xwh[(size_t)N_NODES * OUT_C]; // 25.6 MB, prescaled by dinv
__device__ float  g_dinv[N_NODES];
__device__ int    g_deg[N_NODES];
__device__ int    g_off[N_NODES + 1];
__device__ int    g_cursor[N_NODES];
__device__ int    g_col[2 * N_EDGES];             // 12.8 MB
__device__ int    g_bsum[SCAN_BLOCKS];

__device__ __forceinline__ unsigned h2_to_u32(__half2 h) {
    return *reinterpret_cast<unsigned*>(&h);
}

// ------------------------------------------------------------------
__global__ void k_zero_deg() {
    int i = blockIdx.x * blockDim.x + threadIdx.x;
    if (i < N_NODES) g_deg[i] = 0;
}

// 2 edges per thread; all 4 atomics independent -> MLP 4
__global__ void k_count_deg(const int* __restrict__ ei) {
    int e = (blockIdx.x * blockDim.x + threadIdx.x) * 2;
    if (e + 1 < N_EDGES) {
        int a0 = ei[e],     b0 = ei[N_EDGES + e];
        int a1 = ei[e + 1], b1 = ei[N_EDGES + e + 1];
        atomicAdd(&g_deg[a0], 1);
        atomicAdd(&g_deg[b0], 1);
        atomicAdd(&g_deg[a1], 1);
        atomicAdd(&g_deg[b1], 1);
    } else if (e < N_EDGES) {
        atomicAdd(&g_deg[ei[e]], 1);
        atomicAdd(&g_deg[ei[N_EDGES + e]], 1);
    }
}

// 3a) per-block sums of deg (coalesced)
__global__ void k_block_sum() {
    __shared__ int s[SCAN_CHUNK];
    const int t = threadIdx.x;
    const int i = blockIdx.x * SCAN_CHUNK + t;
    s[t] = (i < N_NODES) ? g_deg[i] : 0;
    __syncthreads();
    for (int d = SCAN_CHUNK / 2; d > 0; d >>= 1) {
        if (t < d) s[t] += s[t + d];
        __syncthreads();
    }
    if (t == 0) g_bsum[blockIdx.x] = s[0];
}

// 3b) per-block apply: block prefix computed inline from g_bsum (98 ints),
//     then block-local scan + write off/cursor/dinv.
__global__ void k_scan_apply() {
    __shared__ int s[SCAN_CHUNK];
    __shared__ int boff;
    const int t = threadIdx.x;
    const int i = blockIdx.x * SCAN_CHUNK + t;
    const int d = (i < N_NODES) ? g_deg[i] : 0;
    s[t] = d;

    // warp 0 computes this block's exclusive prefix over g_bsum
    if (t < 32) {
        int p = 0;
        for (int j = t; j < blockIdx.x; j += 32) p += g_bsum[j];
        #pragma unroll
        for (int o = 16; o > 0; o >>= 1) p += __shfl_down_sync(0xffffffffu, p, o);
        if (t == 0) boff = p;
    }
    __syncthreads();
    for (int k = 1; k < SCAN_CHUNK; k <<= 1) {
        int v = (t >= k) ? s[t - k] : 0;
        __syncthreads();
        s[t] += v;
        __syncthreads();
    }
    if (i < N_NODES) {
        const int excl = s[t] - d;
        g_off[i]    = boff + excl;
        g_cursor[i] = 0;
        g_dinv[i]   = rsqrtf((float)d + 1.0f);
    }
    if (i == N_NODES - 1) g_off[N_NODES] = boff + s[t];   // total = 2*N_EDGES
}

// 4) fill CSR: 2 edges per thread; 4 cursor atomics + 4 off loads issued
//    before any dependent scattered store -> MLP ~8 on long-latency ops.
__global__ void k_fill(const int* __restrict__ ei) {
    int e = (blockIdx.x * blockDim.x + threadIdx.x) * 2;
    if (e + 1 < N_EDGES) {
        int a0 = ei[e],     b0 = ei[N_EDGES + e];
        int a1 = ei[e + 1], b1 = ei[N_EDGES + e + 1];
        int p0 = atomicAdd(&g_cursor[a0], 1);
        int p1 = atomicAdd(&g_cursor[b0], 1);
        int p2 = atomicAdd(&g_cursor[a1], 1);
        int p3 = atomicAdd(&g_cursor[b1], 1);
        int o0 = g_off[a0];
        int o1 = g_off[b0];
        int o2 = g_off[a1];
        int o3 = g_off[b1];
        g_col[o0 + p0] = b0;
        g_col[o1 + p1] = a0;
        g_col[o2 + p2] = b1;
        g_col[o3 + p3] = a1;
    } else if (e < N_EDGES) {
        int a = ei[e];
        int b = ei[N_EDGES + e];
        int pa = atomicAdd(&g_cursor[a], 1);
        int pb = atomicAdd(&g_cursor[b], 1);
        g_col[g_off[a] + pa] = b;
        g_col[g_off[b] + pb] = a;
    }
}

// ------------------------------------------------------------------
// 5) Tensor-core GEMM: xwh = half(dinv[row] * (x @ W)), fp32 accumulate.
#define GEMM_M_BLK 64
#define WT_PAD 8
#define WT_LD (IN_C + WT_PAD)   // 136 halves row stride

__global__ __launch_bounds__(128, 1) void k_gemm(const float* __restrict__ x,
                                                 const float* __restrict__ W) {
    __shared__ __half wt[OUT_C][WT_LD];   // W^T: wt[n][k]

    const int tid  = threadIdx.x;
    const int wid  = tid >> 5;
    const int lane = tid & 31;

    for (int i = tid; i < IN_C * OUT_C; i += 128) {
        int k = i >> 7;
        int n = i & 127;
        wt[n][k] = __float2half(W[(size_t)k * OUT_C + n]);
    }
    __syncthreads();

    const int row_base = blockIdx.x * GEMM_M_BLK + wid * 16;
    const int qr = lane >> 2;
    const int qc = lane & 3;
    const int r0 = row_base + qr;
    const int r1 = r0 + 8;
    const int r0c = (r0 < N_NODES) ? r0 : (N_NODES - 1);
    const int r1c = (r1 < N_NODES) ? r1 : (N_NODES - 1);
    const float* xr0 = x + (size_t)r0c * IN_C;
    const float* xr1 = x + (size_t)r1c * IN_C;

    float acc[16][4];
    #pragma unroll
    for (int nt = 0; nt < 16; nt++)
        #pragma unroll
        for (int q = 0; q < 4; q++) acc[nt][q] = 0.0f;

    #pragma unroll
    for (int ks = 0; ks < IN_C / 16; ks++) {
        const int k0 = ks * 16 + qc * 2;
        float2 f;
        f = *(const float2*)(xr0 + k0);     unsigned a0 = h2_to_u32(__float22half2_rn(f));
        f = *(const float2*)(xr1 + k0);     unsigned a1 = h2_to_u32(__float22half2_rn(f));
        f = *(const float2*)(xr0 + k0 + 8); unsigned a2 = h2_to_u32(__float22half2_rn(f));
        f = *(const float2*)(xr1 + k0 + 8); unsigned a3 = h2_to_u32(__float22half2_rn(f));

        #pragma unroll
        for (int nt = 0; nt < 16; nt++) {
            const int n = nt * 8 + qr;
            unsigned b0 = *(const unsigned*)&wt[n][k0];
            unsigned b1 = *(const unsigned*)&wt[n][k0 + 8];
            asm volatile(
                "mma.sync.aligned.m16n8k16.row.col.f32.f16.f16.f32 "
                "{%0,%1,%2,%3}, {%4,%5,%6,%7}, {%8,%9}, {%0,%1,%2,%3};\n"
                : "+f"(acc[nt][0]), "+f"(acc[nt][1]), "+f"(acc[nt][2]), "+f"(acc[nt][3])
                : "r"(a0), "r"(a1), "r"(a2), "r"(a3), "r"(b0), "r"(b1));
        }
    }

    const float d0 = g_dinv[r0c];
    const float d1 = g_dinv[r1c];
    #pragma unroll
    for (int nt = 0; nt < 16; nt++) {
        const int n = nt * 8 + qc * 2;
        if (r0 < N_NODES) {
            __half2 h = __floats2half2_rn(acc[nt][0] * d0, acc[nt][1] * d0);
            *(__half2*)(g_xwh + (size_t)r0 * OUT_C + n) = h;
        }
        if (r1 < N_NODES) {
            __half2 h = __floats2half2_rn(acc[nt][2] * d1, acc[nt][3] * d1);
            *(__half2*)(g_xwh + (size_t)r1 * OUT_C + n) = h;
        }
    }
}

// ------------------------------------------------------------------
// 6) gather SpMM + self-loop + bias. One warp per destination node.
__global__ void k_gather(const float* __restrict__ b, float* __restrict__ y) {
    const int node = (blockIdx.x * blockDim.x + threadIdx.x) >> 5;
    const int lane = threadIdx.x & 31;
    if (node >= N_NODES) return;

    const int beg = g_off[node];
    const int end = g_off[node + 1];

    float ax = 0.f, ay = 0.f, az = 0.f, aw = 0.f;

    int j = beg;
    for (; j + 8 <= end; j += 8) {
        int c0 = g_col[j + 0], c1 = g_col[j + 1], c2 = g_col[j + 2], c3 = g_col[j + 3];
        int c4 = g_col[j + 4], c5 = g_col[j + 5], c6 = g_col[j + 6], c7 = g_col[j + 7];
        uint2 u0 = ((const uint2*)(g_xwh + (size_t)c0 * OUT_C))[lane];
        uint2 u1 = ((const uint2*)(g_xwh + (size_t)c1 * OUT_C))[lane];
        uint2 u2 = ((const uint2*)(g_xwh + (size_t)c2 * OUT_C))[lane];
        uint2 u3 = ((const uint2*)(g_xwh + (size_t)c3 * OUT_C))[lane];
        uint2 u4 = ((const uint2*)(g_xwh + (size_t)c4 * OUT_C))[lane];
        uint2 u5 = ((const uint2*)(g_xwh + (size_t)c5 * OUT_C))[lane];
        uint2 u6 = ((const uint2*)(g_xwh + (size_t)c6 * OUT_C))[lane];
        uint2 u7 = ((const uint2*)(g_xwh + (size_t)c7 * OUT_C))[lane];
        #define ACCUM(u) { \
            float2 f0 = __half22float2(*(const __half2*)&(u).x); \
            float2 f1 = __half22float2(*(const __half2*)&(u).y); \
            ax += f0.x; ay += f0.y; az += f1.x; aw += f1.y; }
        ACCUM(u0) ACCUM(u1) ACCUM(u2) ACCUM(u3)
        ACCUM(u4) ACCUM(u5) ACCUM(u6) ACCUM(u7)
    }
    for (; j < end; j++) {
        const int c = g_col[j];
        uint2 u = ((const uint2*)(g_xwh + (size_t)c * OUT_C))[lane];
        ACCUM(u)
    }
    {
        uint2 u = ((const uint2*)(g_xwh + (size_t)node * OUT_C))[lane];
        ACCUM(u)
    }
    #undef ACCUM

    const float dn = g_dinv[node];
    const float4 bv = ((const float4*)b)[lane];
    float4 o;
    o.x = dn * ax + bv.x;
    o.y = dn * ay + bv.y;
    o.z = dn * az + bv.z;
    o.w = dn * aw + bv.w;
    ((float4*)(y + (size_t)node * OUT_C))[lane] = o;
}

// ------------------------------------------------------------------
extern "C" void kernel_launch(void* const* d_in, const int* in_sizes, int n_in,
                              void* d_out, int out_size) {
    const float* x  = (const float*)d_in[0];
    const float* W  = (const float*)d_in[1];
    const float* b  = (const float*)d_in[2];
    const int*   ei = (const int*)d_in[3];
    float* y = (float*)d_out;

    // CSR build + dinv
    k_zero_deg<<<(N_NODES + 255) / 256, 256>>>();
    const int ethreads = (N_EDGES + 1) / 2;
    k_count_deg<<<(ethreads + 255) / 256, 256>>>(ei);
    k_block_sum<<<SCAN_BLOCKS, SCAN_CHUNK>>>();
    k_scan_apply<<<SCAN_BLOCKS, SCAN_CHUNK>>>();

    // tensor-core dense projection (needs dinv ready)
    const int gemm_blocks = (N_NODES + GEMM_M_BLK - 1) / GEMM_M_BLK;  // 1563
    k_gemm<<<gemm_blocks, 128>>>(x, W);

    // CSR fill
    k_fill<<<(ethreads + 255) / 256, 256>>>(ei);

    // fused gather + self-loop + bias: one warp per node
    const int gather_blocks = (N_NODES * 32 + 255) / 256;
    k_gather<<<gather_blocks, 256>>>(b, y);
}

// round 8
// speedup vs baseline: 6.6514x; 1.0821x over previous
#include <cuda_runtime.h>
#include <cuda_fp16.h>
#include <cstdint>

#define N_NODES 100000
#define N_EDGES 1600000
#define IN_C 128
#define OUT_C 128

#define SCAN_CHUNK 1024
#define SCAN_BLOCKS ((N_NODES + SCAN_CHUNK - 1) / SCAN_CHUNK)   // 98

// fused gemm+fill kernel geometry
#define GEMM_M_BLK 128
#define GEMM_BLOCKS ((N_NODES + GEMM_M_BLK - 1) / GEMM_M_BLK)   // 782
#define FILL_EPT 2
#define FILL_THREADS 256
#define FILL_BLOCKS (N_EDGES / (FILL_THREADS * FILL_EPT))       // 3125 exact
#define FUSED_BLOCKS (GEMM_BLOCKS + FILL_BLOCKS)                // 3907

#define WT_PAD 8
#define WT_LD (IN_C + WT_PAD)   // 136 halves row stride

// ---- scratch in __device__ globals (no cudaMalloc allowed) ----
__device__ __half g_xwh[(size_t)N_NODES * OUT_C]; // 25.6 MB, prescaled by dinv
__device__ float  g_dinv[N_NODES];
__device__ int    g_deg[N_NODES];
__device__ int    g_off[N_NODES + 1];
__device__ int    g_cursor[N_NODES];              // init to off[i]; atomicAdd -> slot
__device__ int    g_col[2 * N_EDGES];             // 12.8 MB
__device__ int    g_bsum[SCAN_BLOCKS];

__device__ __forceinline__ unsigned h2_to_u32(__half2 h) {
    return *reinterpret_cast<unsigned*>(&h);
}

// ------------------------------------------------------------------
__global__ void k_zero_deg() {
    int i = blockIdx.x * blockDim.x + threadIdx.x;
    if (i < N_NODES) g_deg[i] = 0;
}

__global__ void k_count_deg(const int* __restrict__ ei) {
    int e = (blockIdx.x * blockDim.x + threadIdx.x) * 2;
    if (e + 1 < N_EDGES) {
        int a0 = ei[e],     b0 = ei[N_EDGES + e];
        int a1 = ei[e + 1], b1 = ei[N_EDGES + e + 1];
        atomicAdd(&g_deg[a0], 1);
        atomicAdd(&g_deg[b0], 1);
        atomicAdd(&g_deg[a1], 1);
        atomicAdd(&g_deg[b1], 1);
    } else if (e < N_EDGES) {
        atomicAdd(&g_deg[ei[e]], 1);
        atomicAdd(&g_deg[ei[N_EDGES + e]], 1);
    }
}

// per-block sums of deg (coalesced)
__global__ void k_block_sum() {
    __shared__ int s[SCAN_CHUNK];
    const int t = threadIdx.x;
    const int i = blockIdx.x * SCAN_CHUNK + t;
    s[t] = (i < N_NODES) ? g_deg[i] : 0;
    __syncthreads();
    for (int d = SCAN_CHUNK / 2; d > 0; d >>= 1) {
        if (t < d) s[t] += s[t + d];
        __syncthreads();
    }
    if (t == 0) g_bsum[blockIdx.x] = s[0];
}

// per-block apply: inline prefix over g_bsum, local scan, write off/cursor/dinv
__global__ void k_scan_apply() {
    __shared__ int s[SCAN_CHUNK];
    __shared__ int boff;
    const int t = threadIdx.x;
    const int i = blockIdx.x * SCAN_CHUNK + t;
    const int d = (i < N_NODES) ? g_deg[i] : 0;
    s[t] = d;

    if (t < 32) {
        int p = 0;
        for (int j = t; j < blockIdx.x; j += 32) p += g_bsum[j];
        #pragma unroll
        for (int o = 16; o > 0; o >>= 1) p += __shfl_down_sync(0xffffffffu, p, o);
        if (t == 0) boff = p;
    }
    __syncthreads();
    for (int k = 1; k < SCAN_CHUNK; k <<= 1) {
        int v = (t >= k) ? s[t - k] : 0;
        __syncthreads();
        s[t] += v;
        __syncthreads();
    }
    if (i < N_NODES) {
        const int off = boff + s[t] - d;
        g_off[i]    = off;
        g_cursor[i] = off;                 // fill atomics yield absolute slots
        g_dinv[i]   = rsqrtf((float)d + 1.0f);
    }
    if (i == N_NODES - 1) g_off[N_NODES] = boff + s[t];
}

// ------------------------------------------------------------------
// Fused GEMM + CSR-fill. Block role by index: every 5th block is GEMM
// (782 total), the rest are fill (3125). Both roles co-reside on each SM,
// overlapping tensor/L1 work with L2-atomic work.
__global__ __launch_bounds__(256, 1) void k_gemm_fill(const float* __restrict__ x,
                                                      const float* __restrict__ W,
                                                      const int* __restrict__ ei) {
    const int bid = blockIdx.x;
    const bool is_gemm = (bid % 5 == 0);

    if (!is_gemm) {
        // ---------------- fill role ----------------
        const int fill_id = bid - bid / 5 - 1;
        int e = (fill_id * FILL_THREADS + threadIdx.x) * FILL_EPT;
        if (e + 1 < N_EDGES) {
            int a0 = ei[e],     b0 = ei[N_EDGES + e];
            int a1 = ei[e + 1], b1 = ei[N_EDGES + e + 1];
            int p0 = atomicAdd(&g_cursor[a0], 1);
            int p1 = atomicAdd(&g_cursor[b0], 1);
            int p2 = atomicAdd(&g_cursor[a1], 1);
            int p3 = atomicAdd(&g_cursor[b1], 1);
            g_col[p0] = b0;
            g_col[p1] = a0;
            g_col[p2] = b1;
            g_col[p3] = a1;
        } else if (e < N_EDGES) {
            int a = ei[e];
            int b = ei[N_EDGES + e];
            g_col[atomicAdd(&g_cursor[a], 1)] = b;
            g_col[atomicAdd(&g_cursor[b], 1)] = a;
        }
        return;
    }

    // ---------------- GEMM role ----------------
    __shared__ __half wt[OUT_C][WT_LD];   // W^T: wt[n][k]
    const int gemm_id = bid / 5;
    const int tid  = threadIdx.x;
    const int wid  = tid >> 5;            // 0..7
    const int lane = tid & 31;

    for (int i = tid; i < IN_C * OUT_C; i += 256) {
        int k = i >> 7;
        int n = i & 127;
        wt[n][k] = __float2half(W[(size_t)k * OUT_C + n]);
    }
    __syncthreads();

    const int row_base = gemm_id * GEMM_M_BLK + wid * 16;
    const int qr = lane >> 2;
    const int qc = lane & 3;
    const int r0 = row_base + qr;
    const int r1 = r0 + 8;
    const int r0c = (r0 < N_NODES) ? r0 : (N_NODES - 1);
    const int r1c = (r1 < N_NODES) ? r1 : (N_NODES - 1);
    const float* xr0 = x + (size_t)r0c * IN_C;
    const float* xr1 = x + (size_t)r1c * IN_C;

    float acc[16][4];
    #pragma unroll
    for (int nt = 0; nt < 16; nt++)
        #pragma unroll
        for (int q = 0; q < 4; q++) acc[nt][q] = 0.0f;

    #pragma unroll
    for (int ks = 0; ks < IN_C / 16; ks++) {
        const int k0 = ks * 16 + qc * 2;
        float2 f;
        f = *(const float2*)(xr0 + k0);     unsigned a0 = h2_to_u32(__float22half2_rn(f));
        f = *(const float2*)(xr1 + k0);     unsigned a1 = h2_to_u32(__float22half2_rn(f));
        f = *(const float2*)(xr0 + k0 + 8); unsigned a2 = h2_to_u32(__float22half2_rn(f));
        f = *(const float2*)(xr1 + k0 + 8); unsigned a3 = h2_to_u32(__float22half2_rn(f));

        #pragma unroll
        for (int nt = 0; nt < 16; nt++) {
            const int n = nt * 8 + qr;
            unsigned b0 = *(const unsigned*)&wt[n][k0];
            unsigned b1 = *(const unsigned*)&wt[n][k0 + 8];
            asm volatile(
                "mma.sync.aligned.m16n8k16.row.col.f32.f16.f16.f32 "
                "{%0,%1,%2,%3}, {%4,%5,%6,%7}, {%8,%9}, {%0,%1,%2,%3};\n"
                : "+f"(acc[nt][0]), "+f"(acc[nt][1]), "+f"(acc[nt][2]), "+f"(acc[nt][3])
                : "r"(a0), "r"(a1), "r"(a2), "r"(a3), "r"(b0), "r"(b1));
        }
    }

    const float d0 = g_dinv[r0c];
    const float d1 = g_dinv[r1c];
    #pragma unroll
    for (int nt = 0; nt < 16; nt++) {
        const int n = nt * 8 + qc * 2;
        if (r0 < N_NODES) {
            __half2 h = __floats2half2_rn(acc[nt][0] * d0, acc[nt][1] * d0);
            *(__half2*)(g_xwh + (size_t)r0 * OUT_C + n) = h;
        }
        if (r1 < N_NODES) {
            __half2 h = __floats2half2_rn(acc[nt][2] * d1, acc[nt][3] * d1);
            *(__half2*)(g_xwh + (size_t)r1 * OUT_C + n) = h;
        }
    }
}

// ------------------------------------------------------------------
// gather SpMM + self-loop + bias. One warp per destination node.
__global__ void k_gather(const float* __restrict__ b, float* __restrict__ y) {
    const int node = (blockIdx.x * blockDim.x + threadIdx.x) >> 5;
    const int lane = threadIdx.x & 31;
    if (node >= N_NODES) return;

    const int beg = g_off[node];
    const int end = g_off[node + 1];

    float ax = 0.f, ay = 0.f, az = 0.f, aw = 0.f;

    int j = beg;
    for (; j + 8 <= end; j += 8) {
        int c0 = g_col[j + 0], c1 = g_col[j + 1], c2 = g_col[j + 2], c3 = g_col[j + 3];
        int c4 = g_col[j + 4], c5 = g_col[j + 5], c6 = g_col[j + 6], c7 = g_col[j + 7];
        uint2 u0 = ((const uint2*)(g_xwh + (size_t)c0 * OUT_C))[lane];
        uint2 u1 = ((const uint2*)(g_xwh + (size_t)c1 * OUT_C))[lane];
        uint2 u2 = ((const uint2*)(g_xwh + (size_t)c2 * OUT_C))[lane];
        uint2 u3 = ((const uint2*)(g_xwh + (size_t)c3 * OUT_C))[lane];
        uint2 u4 = ((const uint2*)(g_xwh + (size_t)c4 * OUT_C))[lane];
        uint2 u5 = ((const uint2*)(g_xwh + (size_t)c5 * OUT_C))[lane];
        uint2 u6 = ((const uint2*)(g_xwh + (size_t)c6 * OUT_C))[lane];
        uint2 u7 = ((const uint2*)(g_xwh + (size_t)c7 * OUT_C))[lane];
        #define ACCUM(u) { \
            float2 f0 = __half22float2(*(const __half2*)&(u).x); \
            float2 f1 = __half22float2(*(const __half2*)&(u).y); \
            ax += f0.x; ay += f0.y; az += f1.x; aw += f1.y; }
        ACCUM(u0) ACCUM(u1) ACCUM(u2) ACCUM(u3)
        ACCUM(u4) ACCUM(u5) ACCUM(u6) ACCUM(u7)
    }
    for (; j < end; j++) {
        const int c = g_col[j];
        uint2 u = ((const uint2*)(g_xwh + (size_t)c * OUT_C))[lane];
        ACCUM(u)
    }
    {
        uint2 u = ((const uint2*)(g_xwh + (size_t)node * OUT_C))[lane];
        ACCUM(u)
    }
    #undef ACCUM

    const float dn = g_dinv[node];
    const float4 bv = ((const float4*)b)[lane];
    float4 o;
    o.x = dn * ax + bv.x;
    o.y = dn * ay + bv.y;
    o.z = dn * az + bv.z;
    o.w = dn * aw + bv.w;
    ((float4*)(y + (size_t)node * OUT_C))[lane] = o;
}

// ------------------------------------------------------------------
extern "C" void kernel_launch(void* const* d_in, const int* in_sizes, int n_in,
                              void* d_out, int out_size) {
    const float* x  = (const float*)d_in[0];
    const float* W  = (const float*)d_in[1];
    const float* b  = (const float*)d_in[2];
    const int*   ei = (const int*)d_in[3];
    float* y = (float*)d_out;

    // CSR scaffolding + dinv
    k_zero_deg<<<(N_NODES + 255) / 256, 256>>>();
    const int ethreads = (N_EDGES + 1) / 2;
    k_count_deg<<<(ethreads + 255) / 256, 256>>>(ei);
    k_block_sum<<<SCAN_BLOCKS, SCAN_CHUNK>>>();
    k_scan_apply<<<SCAN_BLOCKS, SCAN_CHUNK>>>();

    // fused tensor-core GEMM + CSR fill (independent workloads, co-scheduled)
    k_gemm_fill<<<FUSED_BLOCKS, 256>>>(x, W, ei);

    // fused gather + self-loop + bias: one warp per node
    const int gather_blocks = (N_NODES * 32 + 255) / 256;
    k_gather<<<gather_blocks, 256>>>(b, y);
}